// round 15
// baseline (speedup 1.0000x reference)
#include <cuda_runtime.h>
#include <cuda_fp16.h>

// Shape fixed by reference setup: N=16, C=3, H=512, W=512, patch=15.
#define N_       16
#define H_       512
#define W_       512
#define PLANE    (H_ * W_)
#define TPB      512
#define NBLK     296                // 148 SMs x 2, balanced strips
#define SROWS    528                // 8 zero-pad rows top + 512 + 8 bottom
#define SD_STRIDE 532               // halves: 8 pad + 512 + 12 pad
#define S4_STRIDE 132               // floats: 2 pad + 128 + 2 pad
#define SMEM1    (24 * SD_STRIDE * 2 + 24 * S4_STRIDE * 4)   // 38208 B

typedef unsigned long long u64;

// Combined scratch: {half2(l,u), half2(v,0)} per pixel. 34.6 MB, BSS-zeroed;
// pad rows never written -> stay zero across graph replays.
__device__ uint2  g_hb[(size_t)N_ * SROWS * W_];
__device__ int    g_flag[NBLK];     // per-strip epoch counters (monotone)
__device__ double g_accum[3];
__device__ int    g_done = 0;

// ---- packed f32x2 helpers (Blackwell FFMA2/FMUL2 via PTX) ----
__device__ __forceinline__ u64 pk(float lo, float hi) {
    u64 r; asm("mov.b64 %0, {%1,%2};" : "=l"(r) : "f"(lo), "f"(hi)); return r;
}
__device__ __forceinline__ void upk(float& lo, float& hi, u64 v) {
    asm("mov.b64 {%0,%1}, %2;" : "=f"(lo), "=f"(hi) : "l"(v));
}
__device__ __forceinline__ u64 fma2(u64 a, u64 b, u64 c) {
    u64 d; asm("fma.rn.f32x2 %0, %1, %2, %3;" : "=l"(d) : "l"(a), "l"(b), "l"(c));
    return d;
}
__device__ __forceinline__ u64 mul2(u64 a, u64 b) {
    u64 d; asm("mul.rn.f32x2 %0, %1, %2;" : "=l"(d) : "l"(a), "l"(b));
    return d;
}

__device__ __forceinline__ float f_func(float t) {
    // reference: cbrt(t) if t > 0.008856 else 7.787*t + 16/116
    float cb = __powf(t, 1.0f / 3.0f);     // MUFU.LG2 + FMUL + MUFU.EX2
    return (t > 0.008856f) ? cb : fmaf(7.787f, t, 16.0f / 116.0f);
}

__device__ __forceinline__ unsigned pack2h(float a, float b) {
    __half2 h = __floats2half2_rn(a, b);
    return *(unsigned*)&h;
}

// ONE kernel: hbox (zero halo) -> scratch -> flag -> wait(blk-1) -> vbox.
// vbox rows shifted down 7 so dependencies are lower-block-index only
// (deadlock-free under any residency).
__global__ void __launch_bounds__(TPB, 2) fused_kernel(
    const float* __restrict__ in, const float* __restrict__ tgt,
    float* __restrict__ out) {
    extern __shared__ char smraw[];
    __half* sdh = (__half*)smraw;                        // [2][4][3][532]
    float*  s4f = (float*)(smraw + 24 * SD_STRIDE * 2);  // [2][4][3][132]

    const int t  = threadIdx.x;
    const int tx = t & 127;
    const int ty = t >> 7;

    // Balanced decomposition: images 0..7 -> 19 strips, images 8..15 -> 18.
    int n, s, S;
    {
        int blk = blockIdx.x;
        if (blk < 152) { n = blk / 19; s = blk - n * 19; S = 19; }
        else { int b = blk - 152; int q = b / 18; n = 8 + q; s = b - q * 18; S = 18; }
    }
    const int h0 = (H_ * s) / S;
    const int sh = (H_ * (s + 1)) / S - h0;              // 26..29

    // Packed constants (XYZ scales folded into matrix rows 0 and 2).
    #define PC(v) pk((v), (v))
    const u64 K00 = PC(0.4124564f / 0.95047f), K01 = PC(0.3575761f / 0.95047f),
              K02 = PC(0.1804375f / 0.95047f);
    const u64 K10 = PC(0.2126729f), K11 = PC(0.7151522f), K12 = PC(0.0721750f);
    const u64 K20 = PC(0.0193339f / 1.08883f), K21 = PC(0.1191920f / 1.08883f),
              K22 = PC(0.9503041f / 1.08883f);
    #undef PC

    auto luv2s = [&](u64 r, u64 g, u64 b,
                     float& L0, float& U0, float& V0,
                     float& L1, float& U1, float& V1) {
        u64 x = fma2(r, K00, fma2(g, K01, mul2(b, K02)));
        u64 y = fma2(r, K10, fma2(g, K11, mul2(b, K12)));
        u64 z = fma2(r, K20, fma2(g, K21, mul2(b, K22)));
        float x0, x1, y0, y1, z0, z1;
        upk(x0, x1, x); upk(y0, y1, y); upk(z0, z1, z);
        float fx0 = f_func(x0), fx1 = f_func(x1);
        float fy0 = f_func(y0), fy1 = f_func(y1);
        float fz0 = f_func(z0), fz1 = f_func(z1);
        L0 = fmaf(116.0f, fy0, -16.0f);
        L1 = fmaf(116.0f, fy1, -16.0f);
        float t0 = 13.0f * L0, t1 = 13.0f * L1;
        U0 = t0 * (fx0 - fy0);  U1 = t1 * (fx1 - fy1);
        V0 = t0 * (fy0 - fz0);  V1 = t1 * (fy1 - fz1);
    };

    // Zero sd/s4 pads (stay zero forever).
    if (t < 480) {
        int p = t / 20, k = t % 20;
        int j = (k < 8) ? k : (512 + k);
        sdh[p * SD_STRIDE + j] = __float2half(0.f);
    }
    if (t < 96) {
        int p = t / 4, k = t % 4;
        int j = (k < 2) ? k : (128 + k);
        s4f[p * S4_STRIDE + j] = 0.f;
    }
    __syncthreads();

    const float4* inA = (const float4*)in;
    const float4* inB = (const float4*)tgt;
    const int P4    = PLANE / 4;                 // 65536
    const int base4 = n * 3 * P4 + tx;

    // =============== phase 1: luv-diff + hbox -> scratch (zero halo) =======
    #pragma unroll 2
    for (int it = 0; it < 8; ++it) {
        if (4 * it >= sh) break;                 // uniform across block
        const int p = it & 1;
        const int planebase = (p * 12 + ty * 3);
        const int rrel = 4 * it + ty;
        const int row  = min(h0 + rrel, H_ - 1);

        {
            const int rb = base4 + row * (W_ / 4);
            float4 ra = __ldcs(&inA[rb]);
            float4 ga = __ldcs(&inA[rb + P4]);
            float4 ba = __ldcs(&inA[rb + 2 * P4]);
            float4 rc = __ldcs(&inB[rb]);
            float4 gc = __ldcs(&inB[rb + P4]);
            float4 bc = __ldcs(&inB[rb + 2 * P4]);

            float d0[4], d1[4], d2[4];
            float La0, Ua0, Va0, La1, Ua1, Va1;
            float Lb0, Ub0, Vb0, Lb1, Ub1, Vb1;
            luv2s(pk(ra.x, ra.y), pk(ga.x, ga.y), pk(ba.x, ba.y),
                  La0, Ua0, Va0, La1, Ua1, Va1);
            luv2s(pk(rc.x, rc.y), pk(gc.x, gc.y), pk(bc.x, bc.y),
                  Lb0, Ub0, Vb0, Lb1, Ub1, Vb1);
            d0[0] = La0 - Lb0; d1[0] = Ua0 - Ub0; d2[0] = Va0 - Vb0;
            d0[1] = La1 - Lb1; d1[1] = Ua1 - Ub1; d2[1] = Va1 - Vb1;
            luv2s(pk(ra.z, ra.w), pk(ga.z, ga.w), pk(ba.z, ba.w),
                  La0, Ua0, Va0, La1, Ua1, Va1);
            luv2s(pk(rc.z, rc.w), pk(gc.z, gc.w), pk(bc.z, bc.w),
                  Lb0, Ub0, Vb0, Lb1, Ub1, Vb1);
            d0[2] = La0 - Lb0; d1[2] = Ua0 - Ub0; d2[2] = Va0 - Vb0;
            d0[3] = La1 - Lb1; d1[3] = Ua1 - Ub1; d2[3] = Va1 - Vb1;

            #pragma unroll
            for (int ch = 0; ch < 3; ch++) {
                const float* d = (ch == 0) ? d0 : (ch == 1) ? d1 : d2;
                *(uint2*)&sdh[(planebase + ch) * SD_STRIDE + 8 + 4 * tx] =
                    make_uint2(pack2h(d[0], d[1]), pack2h(d[2], d[3]));
                s4f[(planebase + ch) * S4_STRIDE + 2 + tx] =
                    (d[0] + d[1]) + (d[2] + d[3]);
            }
        }
        __syncthreads();

        if (rrel < sh) {
            float hbL[4], hbU[4], hbV[4];
            #pragma unroll
            for (int ch = 0; ch < 3; ch++) {
                const __half* sdc = sdh + (planebase + ch) * SD_STRIDE;
                const float*  s4c = s4f + (planebase + ch) * S4_STRIDE;
                float s0 = s4c[tx] + s4c[tx + 1] + s4c[tx + 2] + s4c[tx + 3];
                uint2 Lh = *(const uint2*)&sdc[4 * tx];
                uint2 Rh = *(const uint2*)&sdc[16 + 4 * tx];
                float2 l01 = __half22float2(*(__half2*)&Lh.x);
                float2 l23 = __half22float2(*(__half2*)&Lh.y);
                float2 r01 = __half22float2(*(__half2*)&Rh.x);
                float2 r23 = __half22float2(*(__half2*)&Rh.y);
                float* hb = (ch == 0) ? hbL : (ch == 1) ? hbU : hbV;
                hb[0] = s0 - l01.x;
                hb[1] = hb[0] + r01.x - l01.y;
                hb[2] = hb[1] + r01.y - l23.x;
                hb[3] = hb[2] + r23.x - l23.y;
            }
            size_t gidx = ((size_t)n * SROWS + (h0 + rrel) + 8) * W_ + 4 * tx;
            uint4* wp = (uint4*)&g_hb[gidx];
            wp[0] = make_uint4(pack2h(hbL[0], hbU[0]), pack2h(hbV[0], 0.f),
                               pack2h(hbL[1], hbU[1]), pack2h(hbV[1], 0.f));
            wp[1] = make_uint4(pack2h(hbL[2], hbU[2]), pack2h(hbV[2], 0.f),
                               pack2h(hbL[3], hbU[3]), pack2h(hbV[3], 0.f));
        }
    }

    // =============== flag (release) + wait on lower neighbor ===============
    __threadfence();
    __syncthreads();
    if (t == 0) {
        int my_k = atomicAdd(&g_flag[blockIdx.x], 1) + 1;   // epoch for this launch
        if (s > 0) {
            while (atomicAdd(&g_flag[blockIdx.x - 1], 0) < my_k) __nanosleep(64);
        }
    }
    __syncthreads();

    // =============== phase 2: vbox for rows [h0v, h0v+shv), column t ========
    // Depends only on strips s-1 and s (lower block indices) -> deadlock-free.
    const int h0v = (s == 0) ? 0 : (h0 - 7);
    const int shv = sh + ((s == 0) ? -7 : 0) + ((s == S - 1) ? 7 : 0);

    const uint2* hb = g_hb + ((size_t)n * SROWS + 8) * W_ + t;

    float vs0 = 0.f, vs1 = 0.f, vs2 = 0.f;
    #pragma unroll
    for (int k = -7; k <= 7; k++) {          // window for output row h0v
        uint2 w = __ldcg(&hb[(ptrdiff_t)(h0v + k) * W_]);
        float2 f = __half22float2(*(__half2*)&w.x);
        vs0 += f.x; vs1 += f.y;
        vs2 += __low2float(*(__half2*)&w.y);
    }

    float ac0 = 0.f, ac1 = 0.f, ac2 = 0.f;
    #pragma unroll 4
    for (int j = 0; j < shv; ++j) {
        const int r = h0v + j;
        ac0 = fmaf(vs0, vs0, ac0);
        ac1 = fmaf(vs1, vs1, ac1);
        ac2 = fmaf(vs2, vs2, ac2);
        // Slide window (last iteration's "new" read lands in pad or a racy
        // row whose value is never accumulated -> harmless).
        uint2 wn = __ldcg(&hb[(ptrdiff_t)(r + 8) * W_]);
        uint2 wo = __ldcg(&hb[(ptrdiff_t)(r - 7) * W_]);
        float2 fn = __half22float2(*(__half2*)&wn.x);
        float2 fo = __half22float2(*(__half2*)&wo.x);
        vs0 += fn.x - fo.x;
        vs1 += fn.y - fo.y;
        vs2 += __low2float(*(__half2*)&wn.y) - __low2float(*(__half2*)&wo.y);
    }

    // =============== block reduction + finalize =============================
    #pragma unroll
    for (int o = 16; o > 0; o >>= 1) {
        ac0 += __shfl_down_sync(0xffffffffu, ac0, o);
        ac1 += __shfl_down_sync(0xffffffffu, ac1, o);
        ac2 += __shfl_down_sync(0xffffffffu, ac2, o);
    }
    __syncthreads();
    float* red = s4f;                              // reuse smem
    int wid = t >> 5, lane = t & 31;
    if (lane == 0) { red[wid] = ac0; red[16 + wid] = ac1; red[32 + wid] = ac2; }
    __syncthreads();
    if (t < 3) {
        float sm = 0.f;
        #pragma unroll
        for (int i = 0; i < 16; i++) sm += red[t * 16 + i];
        atomicAdd(&g_accum[t], (double)sm);
    }
    __threadfence();
    __syncthreads();

    __shared__ int is_last;
    if (t == 0) is_last = (atomicAdd(&g_done, 1) == NBLK - 1);
    __syncthreads();
    if (is_last && t == 0) {
        double total = g_accum[0] + g_accum[1] + g_accum[2];
        out[0] = (float)(total / (double)((size_t)N_ * PLANE));
        g_accum[0] = 0.0; g_accum[1] = 0.0; g_accum[2] = 0.0;
        g_done = 0;
    }
}

extern "C" void kernel_launch(void* const* d_in, const int* in_sizes, int n_in,
                              void* d_out, int out_size) {
    const float* in  = (const float*)d_in[0];
    const float* tgt = (const float*)d_in[1];
    float* out = (float*)d_out;

    cudaFuncSetAttribute(fused_kernel,
                         cudaFuncAttributeMaxDynamicSharedMemorySize, SMEM1);
    fused_kernel<<<NBLK, TPB, SMEM1>>>(in, tgt, out);
}